// round 10
// baseline (speedup 1.0000x reference)
#include <cuda_runtime.h>
#include <cuda_bf16.h>
#include <cstdint>
#include <math.h>

// Problem constants
constexpr int Bb = 64, Ss = 512, Hh = 1024, Kd = 2048, Mm = Bb * Ss;
#define NEGV -1e10f

// Scratch (no cudaMalloc allowed)
__device__ float g_WhT[Hh * Bb];      // WhT[h*64+b] = hidden@W^T + W_b + U_b (folded)
__device__ float g_partial[Mm * 4];   // per-(m, n-block) energy partials
__device__ __nv_bfloat16 g_UwB[(size_t)Hh * Kd];    // 4 MB bf16 U_w

// ---------------- GEMM tiling (bf16) ----------------
constexpr int BM = 128, BN = 256, BK = 64;     // BK=64 bf16 = 128B rows
constexpr int NSTG = Kd / BK;                  // 32 K-stages
constexpr int A_BYTES = BM * BK * 2;           // 16 KB
constexpr int B_BYTES = BN * BK * 2;           // 32 KB
constexpr int STG_BYTES = A_BYTES + B_BYTES;   // 48 KB
constexpr int NRING = 4;                       // 4-stage ring -> 1 barrier/stage
constexpr int GEMM_SMEM = NRING * STG_BYTES;   // 192 KB

// ---------------- helpers ----------------
__device__ __forceinline__ uint32_t smem_u32(const void* p) {
    uint32_t a;
    asm("{ .reg .u64 t; cvta.to.shared.u64 t, %1; cvt.u32.u64 %0, t; }" : "=r"(a) : "l"(p));
    return a;
}
__device__ __forceinline__ void cp16(uint32_t dst, const void* src) {
    asm volatile("cp.async.cg.shared.global [%0], [%1], 16;" :: "r"(dst), "l"(src));
}
__device__ __forceinline__ void cp_commit() {
    asm volatile("cp.async.commit_group;" ::: "memory");
}
template <int N> __device__ __forceinline__ void cp_wait() {
    asm volatile("cp.async.wait_group %0;" :: "n"(N) : "memory");
}
__device__ __forceinline__ void ldm4(uint32_t& d0, uint32_t& d1, uint32_t& d2,
                                     uint32_t& d3, uint32_t addr) {
    asm volatile("ldmatrix.sync.aligned.m8n8.x4.shared.b16 {%0,%1,%2,%3}, [%4];"
                 : "=r"(d0), "=r"(d1), "=r"(d2), "=r"(d3) : "r"(addr));
}
__device__ __forceinline__ void mma_bf16(float c[4], uint32_t a0, uint32_t a1,
                                         uint32_t a2, uint32_t a3,
                                         uint32_t b0, uint32_t b1) {
    asm volatile("mma.sync.aligned.m16n8k16.row.col.f32.bf16.bf16.f32 "
                 "{%0,%1,%2,%3}, {%4,%5,%6,%7}, {%8,%9}, {%0,%1,%2,%3};"
                 : "+f"(c[0]), "+f"(c[1]), "+f"(c[2]), "+f"(c[3])
                 : "r"(a0), "r"(a1), "r"(a2), "r"(a3), "r"(b0), "r"(b1));
}
// swizzled 16B-chunk offset within a tile: rows of 8 chunks, chunk column
// XOR'd with (row&7) -> ldmatrix, cp.async STS and fused STS all conflict-free
__device__ __forceinline__ uint32_t tile_off(int row, int kc) {
    return (uint32_t)((row * 8 + (kc ^ (row & 7))) * 16);
}
__device__ __forceinline__ uint4 pack_bf16x8(float4 x, float4 y) {
    __nv_bfloat162 p0 = __float22bfloat162_rn(make_float2(x.x, x.y));
    __nv_bfloat162 p1 = __float22bfloat162_rn(make_float2(x.z, x.w));
    __nv_bfloat162 p2 = __float22bfloat162_rn(make_float2(y.x, y.y));
    __nv_bfloat162 p3 = __float22bfloat162_rn(make_float2(y.z, y.w));
    uint4 o;
    o.x = *reinterpret_cast<unsigned*>(&p0);
    o.y = *reinterpret_cast<unsigned*>(&p1);
    o.z = *reinterpret_cast<unsigned*>(&p2);
    o.w = *reinterpret_cast<unsigned*>(&p3);
    return o;
}

// ---------------------------------------------------------------------------
// Kernel 1 (merged prep): blocks 0-1023 convert U_w fp32->bf16 (1 chunk of 8
// elems per thread); blocks 1024-2047 compute
//   g_WhT[h*64+b] = hidden[b,:]·W_w[h,:] + W_b[h] + U_b[h]
// ---------------------------------------------------------------------------
__global__ void __launch_bounds__(256, 4)
prep_kernel(const float* __restrict__ hidden, const float* __restrict__ W_w,
            const float* __restrict__ W_b, const float* __restrict__ U_b,
            const float* __restrict__ Uw) {
    __shared__ float4 sh[8][256];
    const int tid = threadIdx.x;
    if (blockIdx.x < 1024) {               // U_w conversion: 1024*256 chunks
        const size_t g = (size_t)blockIdx.x * 256 + tid;
        const float4* s = (const float4*)Uw + 2 * g;
        float4 a = s[0], b = s[1];
        ((uint4*)g_UwB)[g] = pack_bf16x8(a, b);
        return;
    }
    const int bid = blockIdx.x - 1024;     // wh part: 128 h-groups x 8 b-groups
    const int h0 = (bid >> 3) * 8, b0 = (bid & 7) * 8;
    for (int i = tid; i < 8 * 256; i += 256) {
        int bl = i >> 8, k4 = i & 255;
        sh[bl][k4] = reinterpret_cast<const float4*>(hidden)[(size_t)(b0 + bl) * 256 + k4];
    }
    __syncthreads();
    const int w = tid >> 5, lane = tid & 31;
    const int h = h0 + w;
    const float4* wrow = reinterpret_cast<const float4*>(W_w) + (size_t)h * 256;
    float acc[8] = {0.f, 0.f, 0.f, 0.f, 0.f, 0.f, 0.f, 0.f};
    for (int k4 = lane; k4 < 256; k4 += 32) {
        float4 wv = wrow[k4];
#pragma unroll
        for (int b = 0; b < 8; ++b) {
            float4 hv = sh[b][k4];
            acc[b] += wv.x * hv.x + wv.y * hv.y + wv.z * hv.z + wv.w * hv.w;
        }
    }
#pragma unroll
    for (int off = 16; off > 0; off >>= 1)
#pragma unroll
        for (int b = 0; b < 8; ++b) acc[b] += __shfl_xor_sync(0xffffffffu, acc[b], off);
    if (lane < 8)
        g_WhT[(size_t)h * 64 + b0 + lane] = acc[lane] + W_b[h] + U_b[h];
}

// ---------------------------------------------------------------------------
// Kernel 2: bf16 mma.sync GEMM (BM=128, BN=256, K=2048) + fused v·tanh epilogue.
// A is converted fp32->bf16 IN the producer (LDG+CVT+STS after the barrier,
// targeting slot (t+2)&3); B streams via cp.async from pre-converted g_UwB.
// 512 threads = 16 warps (4m x 4n), warp tile 32x64, m16n8k16, ldmatrix feeds.
// grid (Hh/256 = 4, Mm/128 = 256): n-block fastest -> A fp32 tile L2 reuse.
// ---------------------------------------------------------------------------
__global__ void __launch_bounds__(512, 1)
gemm_energy_mma(const float* __restrict__ enc, const float* __restrict__ v) {
    extern __shared__ char smem[];
    const uint32_t sbase = smem_u32(smem);

    const int tid = threadIdx.x;
    const int n0 = blockIdx.x * BN;
    const int m0 = blockIdx.y * BM;

    // ---- producer geometry: 512 threads; per stage each thread owns
    //   A: 2 chunks (rows crow, crow+64; 8 elems each) -> LDG fp32 + CVT + STS
    //   B: 4 chunks via cp.async (bf16)
    const int crow = tid >> 3, ckc = tid & 7;         // crow 0..63
    const char* srcB0 = (const char*)(g_UwB + (size_t)(n0 + crow) * Kd) + ckc * 16;
    const uint32_t dstA0 = tile_off(crow, ckc);
    const uint32_t dstB0 = (uint32_t)A_BYTES + tile_off(crow, ckc);
    constexpr size_t SRC_STEP = (size_t)64 * Kd * 2;  // 64 bf16 rows
    constexpr uint32_t DST_STEP = 64 * 8 * 16;        // 8192 B
    // fp32 A sources (8 floats per chunk)
    const float* srcA_f0 = enc + (size_t)(m0 + crow) * Kd + ckc * 8;
    const float* srcA_f1 = enc + (size_t)(m0 + crow + 64) * Kd + ckc * 8;

    auto load_B = [&](int t) {
        const uint32_t base = sbase + (uint32_t)(t & (NRING - 1)) * STG_BYTES;
        const size_t ko = (size_t)t * (BK * 2);       // 128 B per stage
#pragma unroll
        for (int i = 0; i < 4; ++i)
            cp16(base + dstB0 + i * DST_STEP, srcB0 + ko + i * SRC_STEP);
        cp_commit();
    };
    auto load_conv_A = [&](int t) {                   // prologue-only (synchronous)
        char* base = smem + (size_t)(t & (NRING - 1)) * STG_BYTES;
        const float4* s0 = (const float4*)(srcA_f0 + (size_t)t * BK);
        const float4* s1 = (const float4*)(srcA_f1 + (size_t)t * BK);
        *(uint4*)(base + dstA0) = pack_bf16x8(s0[0], s0[1]);
        *(uint4*)(base + dstA0 + DST_STEP) = pack_bf16x8(s1[0], s1[1]);
    };

    load_conv_A(0);
    load_conv_A(1);
    load_B(0);
    load_B(1);

    const int wid = tid >> 5, lane = tid & 31;
    const int wm = wid >> 2, wn = wid & 3;     // warp grid 4(m) x 4(n)
    const int gid = lane >> 2, tig = lane & 3;

    // ---- ldmatrix per-lane addresses (canonical bf16 m16n8k16 fragments)
    const uint32_t s7 = lane & 7;
    const uint32_t kcA = lane >> 4;            // 0/1
    const uint32_t kcB = (lane >> 3) & 1;      // 0/1
    uint32_t offA[2], offB[4];
#pragma unroll
    for (int mt = 0; mt < 2; ++mt)
        offA[mt] = (uint32_t)(wm * 32 + mt * 16 + (lane & 15)) * 128;
    const uint32_t rowBoff = (lane & 7) + ((lane >> 4) << 3);
#pragma unroll
    for (int p = 0; p < 4; ++p)
        offB[p] = (uint32_t)A_BYTES + (uint32_t)(wn * 64 + p * 16 + rowBoff) * 128;
    uint32_t coffA[4], coffB[4];
#pragma unroll
    for (int ks = 0; ks < 4; ++ks) {           // ks = one k16 step = chunks 2ks, 2ks+1
        coffA[ks] = ((2 * ks + kcA) ^ s7) * 16;
        coffB[ks] = ((2 * ks + kcB) ^ s7) * 16;
    }

    float c[2][8][4];
#pragma unroll
    for (int mt = 0; mt < 2; ++mt)
#pragma unroll
        for (int nt = 0; nt < 8; ++nt)
#pragma unroll
            for (int k = 0; k < 4; ++k) c[mt][nt][k] = 0.f;

    for (int t = 0; t < NSTG; ++t) {
        const bool pf = (t + 2 < NSTG);
        if (pf) { load_B(t + 2); cp_wait<2>(); }
        else if (t + 1 < NSTG) cp_wait<1>();
        else cp_wait<0>();
        __syncthreads();
        // A(t+2) fused convert: slot (t+2)&3's old contents (stage t-2) were
        // last read before barrier(t-1) < barrier(t) -> race-free; readers of
        // stage t+2 see the STS via barrier(t+2).
        float4 ax0, ax1, ay0, ay1;
        if (pf) {
            const float4* s0 = (const float4*)(srcA_f0 + (size_t)(t + 2) * BK);
            const float4* s1 = (const float4*)(srcA_f1 + (size_t)(t + 2) * BK);
            ax0 = s0[0]; ax1 = s0[1];
            ay0 = s1[0]; ay1 = s1[1];
        }

        const uint32_t stb = sbase + (uint32_t)(t & (NRING - 1)) * STG_BYTES;

#pragma unroll
        for (int ks = 0; ks < 4; ++ks) {
            uint32_t a[2][4];
#pragma unroll
            for (int mt = 0; mt < 2; ++mt)
                ldm4(a[mt][0], a[mt][1], a[mt][2], a[mt][3],
                     stb + offA[mt] + coffA[ks]);
            uint32_t b[8][2];
#pragma unroll
            for (int p = 0; p < 4; ++p)
                ldm4(b[2 * p][0], b[2 * p][1], b[2 * p + 1][0], b[2 * p + 1][1],
                     stb + offB[p] + coffB[ks]);
#pragma unroll
            for (int mt = 0; mt < 2; ++mt)
#pragma unroll
                for (int nt = 0; nt < 8; ++nt)
                    mma_bf16(c[mt][nt], a[mt][0], a[mt][1], a[mt][2], a[mt][3],
                             b[nt][0], b[nt][1]);
            if (ks == 1 && pf) {      // convert+store mid-stage (LDG latency hidden)
                char* base = smem + (size_t)((t + 2) & (NRING - 1)) * STG_BYTES;
                *(uint4*)(base + dstA0) = pack_bf16x8(ax0, ax1);
                *(uint4*)(base + dstA0 + DST_STEP) = pack_bf16x8(ay0, ay1);
            }
        }
    }

    // ---- fused epilogue: pe = sum over held cols of v[h]*tanh(C + WhT[h][b])
    float pe[2][2];
#pragma unroll
    for (int mt = 0; mt < 2; ++mt) { pe[mt][0] = 0.f; pe[mt][1] = 0.f; }

#pragma unroll
    for (int nt = 0; nt < 8; ++nt) {
        const int h0 = n0 + wn * 64 + nt * 8 + 2 * tig;
        const float vh0 = __ldg(&v[h0]);
        const float vh1 = __ldg(&v[h0 + 1]);
#pragma unroll
        for (int mt = 0; mt < 2; ++mt) {
#pragma unroll
            for (int half = 0; half < 2; ++half) {
                const int b = (wm * 32 + mt * 16 + half * 8 + gid) & 63;  // (m0+row)&63
                const float w0 = __ldg(&g_WhT[(size_t)h0 * 64 + b]);
                const float w1 = __ldg(&g_WhT[(size_t)(h0 + 1) * 64 + b]);
                pe[mt][half] += vh0 * tanhf(c[mt][nt][half * 2 + 0] + w0)
                              + vh1 * tanhf(c[mt][nt][half * 2 + 1] + w1);
            }
        }
    }

    // cross-warp reduction over the 4 n-warps (wn)
    __syncthreads();
    float* sred = (float*)smem;
#pragma unroll
    for (int mt = 0; mt < 2; ++mt)
#pragma unroll
        for (int half = 0; half < 2; ++half) {
            float s = pe[mt][half];
            s += __shfl_xor_sync(0xffffffffu, s, 1);
            s += __shfl_xor_sync(0xffffffffu, s, 2);
            if (tig == 0)
                sred[wn * 128 + wm * 32 + mt * 16 + half * 8 + gid] = s;
        }
    __syncthreads();
    if (tid < 128) {
        float s = sred[tid] + sred[128 + tid] + sred[256 + tid] + sred[384 + tid];
        g_partial[(size_t)(m0 + tid) * 4 + blockIdx.x] = s;
    }
}

// ---------------------------------------------------------------------------
// Kernel 3: masked softmax over S per batch. grid 64, block 512.
// ---------------------------------------------------------------------------
__global__ void softmax_kernel(const int* __restrict__ mask, float* __restrict__ out) {
    const int b = blockIdx.x;
    const int s = threadIdx.x;
    const int m = s * Bb + b;
    float e = g_partial[(size_t)m * 4 + 0] + g_partial[(size_t)m * 4 + 1]
            + g_partial[(size_t)m * 4 + 2] + g_partial[(size_t)m * 4 + 3];
    if (mask[b * Ss + s] != 0) e = NEGV;

    __shared__ float red[512];
    red[s] = e;
    __syncthreads();
    for (int off = 256; off > 0; off >>= 1) {
        if (s < off) red[s] = fmaxf(red[s], red[s + off]);
        __syncthreads();
    }
    const float mx = red[0];
    __syncthreads();
    const float ex = __expf(e - mx);
    red[s] = ex;
    __syncthreads();
    for (int off = 256; off > 0; off >>= 1) {
        if (s < off) red[s] += red[s + off];
        __syncthreads();
    }
    out[b * Ss + s] = ex / red[0];
}

// ---------------------------------------------------------------------------
extern "C" void kernel_launch(void* const* d_in, const int* in_sizes, int n_in,
                              void* d_out, int out_size) {
    const float* hidden = (const float*)d_in[0];
    const float* enc    = (const float*)d_in[1];   // [S,B,2H] == [Mm,Kd]
    const int*   mask   = (const int*)d_in[2];
    const float* W_w    = (const float*)d_in[3];
    const float* W_b    = (const float*)d_in[4];
    const float* U_w    = (const float*)d_in[5];
    const float* U_b    = (const float*)d_in[6];
    const float* v_w    = (const float*)d_in[7];
    float* out = (float*)d_out;

    cudaFuncSetAttribute(gemm_energy_mma, cudaFuncAttributeMaxDynamicSharedMemorySize,
                         GEMM_SMEM);

    prep_kernel<<<2048, 256>>>(hidden, W_w, W_b, U_b, U_w);
    gemm_energy_mma<<<dim3(Hh / BN, Mm / BM), 512, GEMM_SMEM>>>(enc, v_w);
    softmax_kernel<<<Bb, 512>>>(mask, out);
}

// round 12
// speedup vs baseline: 1.0783x; 1.0783x over previous
#include <cuda_runtime.h>
#include <cuda_bf16.h>
#include <cstdint>
#include <math.h>

// Problem constants
constexpr int Bb = 64, Ss = 512, Hh = 1024, Kd = 2048, Mm = Bb * Ss;
#define NEGV -1e10f

// Scratch (no cudaMalloc allowed)
__device__ float g_WhT[Hh * Bb];      // WhT[h*64+b] = hidden@W^T + W_b + U_b (folded)
__device__ float g_partial[Mm * 8];   // per-(m, n-block) energy partials
__device__ __nv_bfloat16 g_encB[(size_t)Mm * Kd];   // 128 MB bf16 enc
__device__ __nv_bfloat16 g_UwB[(size_t)Hh * Kd];    // 4 MB bf16 U_w

// ---------------- GEMM tiling (bf16) ----------------
constexpr int BM = 128, BN = 128, BK = 64;     // BK=64 bf16 = 128B rows
constexpr int NSTG = Kd / BK;                  // 32 K-stages
constexpr int A_BYTES = BM * BK * 2;           // 16 KB
constexpr int B_BYTES = BN * BK * 2;           // 16 KB
constexpr int STG_BYTES = A_BYTES + B_BYTES;   // 32 KB
constexpr int NRING = 3;                       // ring-3; load AFTER compute -> safe
constexpr int GEMM_SMEM = NRING * STG_BYTES;   // 96 KB -> 2 CTAs/SM

// prep kernel block ranges
constexpr int ENC_BLK = (Mm * (size_t)Kd) / (8 * 256);  // 32768
constexpr int UW_BLK  = (Hh * (size_t)Kd) / (8 * 256);  // 1024
constexpr int WH_BLK  = (Hh / 8) * (Bb / 8);            // 1024

// ---------------- helpers ----------------
__device__ __forceinline__ uint32_t smem_u32(const void* p) {
    uint32_t a;
    asm("{ .reg .u64 t; cvta.to.shared.u64 t, %1; cvt.u32.u64 %0, t; }" : "=r"(a) : "l"(p));
    return a;
}
__device__ __forceinline__ void cp16(uint32_t dst, const void* src) {
    asm volatile("cp.async.cg.shared.global [%0], [%1], 16;" :: "r"(dst), "l"(src));
}
__device__ __forceinline__ void cp_commit() {
    asm volatile("cp.async.commit_group;" ::: "memory");
}
template <int N> __device__ __forceinline__ void cp_wait() {
    asm volatile("cp.async.wait_group %0;" :: "n"(N) : "memory");
}
__device__ __forceinline__ void ldm4(uint32_t& d0, uint32_t& d1, uint32_t& d2,
                                     uint32_t& d3, uint32_t addr) {
    asm volatile("ldmatrix.sync.aligned.m8n8.x4.shared.b16 {%0,%1,%2,%3}, [%4];"
                 : "=r"(d0), "=r"(d1), "=r"(d2), "=r"(d3) : "r"(addr));
}
__device__ __forceinline__ void mma_bf16(float c[4], uint32_t a0, uint32_t a1,
                                         uint32_t a2, uint32_t a3,
                                         uint32_t b0, uint32_t b1) {
    asm volatile("mma.sync.aligned.m16n8k16.row.col.f32.bf16.bf16.f32 "
                 "{%0,%1,%2,%3}, {%4,%5,%6,%7}, {%8,%9}, {%0,%1,%2,%3};"
                 : "+f"(c[0]), "+f"(c[1]), "+f"(c[2]), "+f"(c[3])
                 : "r"(a0), "r"(a1), "r"(a2), "r"(a3), "r"(b0), "r"(b1));
}
// swizzled 16B-chunk offset within a tile: rows of 8 chunks, chunk column
// XOR'd with (row&7) -> ldmatrix and cp.async STS both conflict-free
__device__ __forceinline__ uint32_t tile_off(int row, int kc) {
    return (uint32_t)((row * 8 + (kc ^ (row & 7))) * 16);
}
__device__ __forceinline__ uint4 pack_bf16x8(float4 x, float4 y) {
    __nv_bfloat162 p0 = __float22bfloat162_rn(make_float2(x.x, x.y));
    __nv_bfloat162 p1 = __float22bfloat162_rn(make_float2(x.z, x.w));
    __nv_bfloat162 p2 = __float22bfloat162_rn(make_float2(y.x, y.y));
    __nv_bfloat162 p3 = __float22bfloat162_rn(make_float2(y.z, y.w));
    uint4 o;
    o.x = *reinterpret_cast<unsigned*>(&p0);
    o.y = *reinterpret_cast<unsigned*>(&p1);
    o.z = *reinterpret_cast<unsigned*>(&p2);
    o.w = *reinterpret_cast<unsigned*>(&p3);
    return o;
}

// ---------------------------------------------------------------------------
// Kernel 1 (merged prep, ONE launch):
//   blocks [0, ENC_BLK)                 : enc fp32 -> bf16
//   blocks [ENC_BLK, ENC_BLK+UW_BLK)    : U_w fp32 -> bf16
//   blocks [ENC_BLK+UW_BLK, ...+WH_BLK) : g_WhT[h*64+b] = hidden·W_w + W_b + U_b
// ---------------------------------------------------------------------------
__global__ void __launch_bounds__(256, 4)
prep_kernel(const float* __restrict__ enc, const float* __restrict__ Uw,
            const float* __restrict__ hidden, const float* __restrict__ W_w,
            const float* __restrict__ W_b, const float* __restrict__ U_b) {
    __shared__ float4 sh[8][256];
    const int tid = threadIdx.x;
    if (blockIdx.x < ENC_BLK) {
        const size_t g = (size_t)blockIdx.x * 256 + tid;
        const float4* s = (const float4*)enc + 2 * g;
        ((uint4*)g_encB)[g] = pack_bf16x8(s[0], s[1]);
        return;
    }
    if (blockIdx.x < ENC_BLK + UW_BLK) {
        const size_t g = (size_t)(blockIdx.x - ENC_BLK) * 256 + tid;
        const float4* s = (const float4*)Uw + 2 * g;
        ((uint4*)g_UwB)[g] = pack_bf16x8(s[0], s[1]);
        return;
    }
    const int bid = blockIdx.x - ENC_BLK - UW_BLK;   // wh: 128 h-grp x 8 b-grp
    const int h0 = (bid >> 3) * 8, b0 = (bid & 7) * 8;
    for (int i = tid; i < 8 * 256; i += 256) {
        int bl = i >> 8, k4 = i & 255;
        sh[bl][k4] = reinterpret_cast<const float4*>(hidden)[(size_t)(b0 + bl) * 256 + k4];
    }
    __syncthreads();
    const int w = tid >> 5, lane = tid & 31;
    const int h = h0 + w;
    const float4* wrow = reinterpret_cast<const float4*>(W_w) + (size_t)h * 256;
    float acc[8] = {0.f, 0.f, 0.f, 0.f, 0.f, 0.f, 0.f, 0.f};
    for (int k4 = lane; k4 < 256; k4 += 32) {
        float4 wv = wrow[k4];
#pragma unroll
        for (int b = 0; b < 8; ++b) {
            float4 hv = sh[b][k4];
            acc[b] += wv.x * hv.x + wv.y * hv.y + wv.z * hv.z + wv.w * hv.w;
        }
    }
#pragma unroll
    for (int off = 16; off > 0; off >>= 1)
#pragma unroll
        for (int b = 0; b < 8; ++b) acc[b] += __shfl_xor_sync(0xffffffffu, acc[b], off);
    if (lane < 8)
        g_WhT[(size_t)h * 64 + b0 + lane] = acc[lane] + W_b[h] + U_b[h];
}

// ---------------------------------------------------------------------------
// Kernel 2: bf16 mma.sync GEMM (BM=128, BN=128, K=2048) + fused v·tanh epilogue.
// 256 threads = 8 warps (2m x 4n), warp tile 64x32, m16n8k16, ldmatrix feeds.
// ring-3, ONE barrier/stage, loads issued AFTER compute(t):
//   a thread issuing load(t+2) has passed barrier(t), so all threads finished
//   compute(t-1); slot (t+2)%3 == (t-1)%3 has no remaining readers. Race-free.
// 96KB smem + 2 CTAs/SM so cross-CTA interleaving hides barrier/ldm stalls.
// grid (Hh/128 = 8, Mm/128 = 256): n-block fastest -> A tile L2 reuse.
// ---------------------------------------------------------------------------
__global__ void __launch_bounds__(256, 2)
gemm_energy_mma(const float* __restrict__ v) {
    extern __shared__ char smem[];
    const uint32_t sbase = smem_u32(smem);

    const int tid = threadIdx.x;
    const int n0 = blockIdx.x * BN;
    const int m0 = blockIdx.y * BM;

    // ---- cp.async geometry: 256 threads, 8 chunks/thread (4 A + 4 B).
    const int crow = tid >> 3, ckc = tid & 7;          // crow 0..31
    const char* srcA0 = (const char*)(g_encB + (size_t)(m0 + crow) * Kd) + ckc * 16;
    const char* srcB0 = (const char*)(g_UwB + (size_t)(n0 + crow) * Kd) + ckc * 16;
    const uint32_t dstA0 = tile_off(crow, ckc);
    const uint32_t dstB0 = (uint32_t)A_BYTES + tile_off(crow, ckc);
    constexpr size_t SRC_STEP = (size_t)32 * Kd * 2;   // 32 bf16 rows
    constexpr uint32_t DST_STEP = 32 * 8 * 16;         // 4096 B

    auto load_stage = [&](int t) {
        const uint32_t base = sbase + (uint32_t)(t % NRING) * STG_BYTES;
        const size_t ko = (size_t)t * (BK * 2);        // 128 B per stage
#pragma unroll
        for (int i = 0; i < 4; ++i)
            cp16(base + dstA0 + i * DST_STEP, srcA0 + ko + i * SRC_STEP);
#pragma unroll
        for (int i = 0; i < 4; ++i)
            cp16(base + dstB0 + i * DST_STEP, srcB0 + ko + i * SRC_STEP);
        cp_commit();
    };

    load_stage(0);
    load_stage(1);

    const int wid = tid >> 5, lane = tid & 31;
    const int wm = wid >> 2, wn = wid & 3;     // warp grid 2(m) x 4(n)
    const int gid = lane >> 2, tig = lane & 3;

    // ---- ldmatrix per-lane addresses (canonical bf16 m16n8k16 fragments)
    const uint32_t s7 = lane & 7;
    const uint32_t kcA = lane >> 4;            // 0/1
    const uint32_t kcB = (lane >> 3) & 1;      // 0/1
    uint32_t offA[4], offB[2];
#pragma unroll
    for (int mt = 0; mt < 4; ++mt)
        offA[mt] = (uint32_t)(wm * 64 + mt * 16 + (lane & 15)) * 128;
    const uint32_t rowBoff = (lane & 7) + ((lane >> 4) << 3);
#pragma unroll
    for (int p = 0; p < 2; ++p)
        offB[p] = (uint32_t)A_BYTES + (uint32_t)(wn * 32 + p * 16 + rowBoff) * 128;
    uint32_t coffA[4], coffB[4];
#pragma unroll
    for (int ks = 0; ks < 4; ++ks) {           // ks = one k16 step = chunks 2ks, 2ks+1
        coffA[ks] = ((2 * ks + kcA) ^ s7) * 16;
        coffB[ks] = ((2 * ks + kcB) ^ s7) * 16;
    }

    float c[4][4][4];
#pragma unroll
    for (int mt = 0; mt < 4; ++mt)
#pragma unroll
        for (int nt = 0; nt < 4; ++nt)
#pragma unroll
            for (int k = 0; k < 4; ++k) c[mt][nt][k] = 0.f;

    for (int t = 0; t < NSTG; ++t) {
        // stage t resident: 2 groups can be pending (t, t+1) -> wait<1>
        if (t < NSTG - 1) cp_wait<1>();
        else cp_wait<0>();
        __syncthreads();

        const uint32_t stb = sbase + (uint32_t)(t % NRING) * STG_BYTES;

#pragma unroll
        for (int ks = 0; ks < 4; ++ks) {
            uint32_t a[4][4];
#pragma unroll
            for (int mt = 0; mt < 4; ++mt)
                ldm4(a[mt][0], a[mt][1], a[mt][2], a[mt][3],
                     stb + offA[mt] + coffA[ks]);
            uint32_t b[4][2];
#pragma unroll
            for (int p = 0; p < 2; ++p)
                ldm4(b[2 * p][0], b[2 * p][1], b[2 * p + 1][0], b[2 * p + 1][1],
                     stb + offB[p] + coffB[ks]);
#pragma unroll
            for (int mt = 0; mt < 4; ++mt)
#pragma unroll
                for (int nt = 0; nt < 4; ++nt)
                    mma_bf16(c[mt][nt], a[mt][0], a[mt][1], a[mt][2], a[mt][3],
                             b[nt][0], b[nt][1]);
        }

        // prefetch AFTER compute(t): past barrier(t) -> compute(t-1) done in
        // all threads -> slot (t+2)%3 == (t-1)%3 safe to overwrite.
        if (t + 2 < NSTG) load_stage(t + 2);
    }

    // ---- fused epilogue: pe = sum over held cols of v[h]*tanh(C + WhT[h][b])
    float pe[4][2];
#pragma unroll
    for (int mt = 0; mt < 4; ++mt) { pe[mt][0] = 0.f; pe[mt][1] = 0.f; }

#pragma unroll
    for (int nt = 0; nt < 4; ++nt) {
        const int h0 = n0 + wn * 32 + nt * 8 + 2 * tig;
        const float vh0 = __ldg(&v[h0]);
        const float vh1 = __ldg(&v[h0 + 1]);
#pragma unroll
        for (int mt = 0; mt < 4; ++mt) {
#pragma unroll
            for (int half = 0; half < 2; ++half) {
                const int b = (mt * 16 + half * 8 + gid) & 63;  // (m0+row)&63; wm*64≡0 (mod 64)
                const float w0 = __ldg(&g_WhT[(size_t)h0 * 64 + b]);
                const float w1 = __ldg(&g_WhT[(size_t)(h0 + 1) * 64 + b]);
                pe[mt][half] += vh0 * tanhf(c[mt][nt][half * 2 + 0] + w0)
                              + vh1 * tanhf(c[mt][nt][half * 2 + 1] + w1);
            }
        }
    }

    // cross-warp reduction over the 4 n-warps (wn)
    __syncthreads();
    float* sred = (float*)smem;
#pragma unroll
    for (int mt = 0; mt < 4; ++mt)
#pragma unroll
        for (int half = 0; half < 2; ++half) {
            float s = pe[mt][half];
            s += __shfl_xor_sync(0xffffffffu, s, 1);
            s += __shfl_xor_sync(0xffffffffu, s, 2);
            if (tig == 0)
                sred[wn * 128 + wm * 64 + mt * 16 + half * 8 + gid] = s;
        }
    __syncthreads();
    if (tid < 128) {
        float s = sred[tid] + sred[128 + tid] + sred[256 + tid] + sred[384 + tid];
        g_partial[(size_t)(m0 + tid) * 8 + blockIdx.x] = s;
    }
}

// ---------------------------------------------------------------------------
// Kernel 3: masked softmax over S per batch. grid 64, block 512.
// ---------------------------------------------------------------------------
__global__ void softmax_kernel(const int* __restrict__ mask, float* __restrict__ out) {
    const int b = blockIdx.x;
    const int s = threadIdx.x;
    const int m = s * Bb + b;
    float e = 0.f;
#pragma unroll
    for (int nb = 0; nb < 8; ++nb) e += g_partial[(size_t)m * 8 + nb];
    if (mask[b * Ss + s] != 0) e = NEGV;

    __shared__ float red[512];
    red[s] = e;
    __syncthreads();
    for (int off = 256; off > 0; off >>= 1) {
        if (s < off) red[s] = fmaxf(red[s], red[s + off]);
        __syncthreads();
    }
    const float mx = red[0];
    __syncthreads();
    const float ex = __expf(e - mx);
    red[s] = ex;
    __syncthreads();
    for (int off = 256; off > 0; off >>= 1) {
        if (s < off) red[s] += red[s + off];
        __syncthreads();
    }
    out[b * Ss + s] = ex / red[0];
}

// ---------------------------------------------------------------------------
extern "C" void kernel_launch(void* const* d_in, const int* in_sizes, int n_in,
                              void* d_out, int out_size) {
    const float* hidden = (const float*)d_in[0];
    const float* enc    = (const float*)d_in[1];   // [S,B,2H] == [Mm,Kd]
    const int*   mask   = (const int*)d_in[2];
    const float* W_w    = (const float*)d_in[3];
    const float* W_b    = (const float*)d_in[4];
    const float* U_w    = (const float*)d_in[5];
    const float* U_b    = (const float*)d_in[6];
    const float* v_w    = (const float*)d_in[7];
    float* out = (float*)d_out;

    cudaFuncSetAttribute(gemm_energy_mma, cudaFuncAttributeMaxDynamicSharedMemorySize,
                         GEMM_SMEM);

    prep_kernel<<<ENC_BLK + UW_BLK + WH_BLK, 256>>>(enc, U_w, hidden, W_w, W_b, U_b);
    gemm_energy_mma<<<dim3(Hh / BN, Mm / BM), 256, GEMM_SMEM>>>(v_w);
    softmax_kernel<<<Bb, 512>>>(mask, out);
}

// round 14
// speedup vs baseline: 1.1329x; 1.0506x over previous
#include <cuda_runtime.h>
#include <cuda_bf16.h>
#include <cstdint>
#include <math.h>

// Problem constants
constexpr int Bb = 64, Ss = 512, Hh = 1024, Kd = 2048, Mm = Bb * Ss;
#define NEGV -1e10f

// Scratch (no cudaMalloc allowed)
__device__ float g_WhT[Hh * Bb];      // WhT[h*64+b] = hidden@W^T + W_b + U_b (folded)
__device__ float g_partial[Mm * 8];   // per-(m, n-block) energy partials
__device__ __nv_bfloat16 g_encB[(size_t)Mm * Kd];   // 128 MB bf16 enc
__device__ __nv_bfloat16 g_UwB[(size_t)Hh * Kd];    // 4 MB bf16 U_w

// ---------------- GEMM tiling (bf16) ----------------
constexpr int BM = 128, BN = 128, BK = 64;     // BK=64 bf16 = 128B rows
constexpr int NSTG = Kd / BK;                  // 32 K-stages
constexpr int A_BYTES = BM * BK * 2;           // 16 KB
constexpr int B_BYTES = BN * BK * 2;           // 16 KB
constexpr int STG_BYTES = A_BYTES + B_BYTES;   // 32 KB
constexpr int NRING = 3;                       // ring-3; load AFTER compute -> safe
constexpr int GEMM_SMEM = NRING * STG_BYTES;   // 96 KB -> 2 CTAs/SM

// prep kernel block ranges (merged single launch, R12-validated)
constexpr int ENC_BLK = (Mm * (size_t)Kd) / (8 * 256);  // 32768
constexpr int UW_BLK  = (Hh * (size_t)Kd) / (8 * 256);  // 1024
constexpr int WH_BLK  = (Hh / 8) * (Bb / 8);            // 1024

// ---------------- helpers ----------------
__device__ __forceinline__ uint32_t smem_u32(const void* p) {
    uint32_t a;
    asm("{ .reg .u64 t; cvta.to.shared.u64 t, %1; cvt.u32.u64 %0, t; }" : "=r"(a) : "l"(p));
    return a;
}
__device__ __forceinline__ void cp16(uint32_t dst, const void* src) {
    asm volatile("cp.async.cg.shared.global [%0], [%1], 16;" :: "r"(dst), "l"(src));
}
__device__ __forceinline__ void cp_commit() {
    asm volatile("cp.async.commit_group;" ::: "memory");
}
template <int N> __device__ __forceinline__ void cp_wait() {
    asm volatile("cp.async.wait_group %0;" :: "n"(N) : "memory");
}
__device__ __forceinline__ void ldm4(uint32_t& d0, uint32_t& d1, uint32_t& d2,
                                     uint32_t& d3, uint32_t addr) {
    asm volatile("ldmatrix.sync.aligned.m8n8.x4.shared.b16 {%0,%1,%2,%3}, [%4];"
                 : "=r"(d0), "=r"(d1), "=r"(d2), "=r"(d3) : "r"(addr));
}
__device__ __forceinline__ void mma_bf16(float c[4], uint32_t a0, uint32_t a1,
                                         uint32_t a2, uint32_t a3,
                                         uint32_t b0, uint32_t b1) {
    asm volatile("mma.sync.aligned.m16n8k16.row.col.f32.bf16.bf16.f32 "
                 "{%0,%1,%2,%3}, {%4,%5,%6,%7}, {%8,%9}, {%0,%1,%2,%3};"
                 : "+f"(c[0]), "+f"(c[1]), "+f"(c[2]), "+f"(c[3])
                 : "r"(a0), "r"(a1), "r"(a2), "r"(a3), "r"(b0), "r"(b1));
}
// swizzled 16B-chunk offset within a tile: rows of 8 chunks, chunk column
// XOR'd with (row&7) -> ldmatrix and cp.async STS both conflict-free
__device__ __forceinline__ uint32_t tile_off(int row, int kc) {
    return (uint32_t)((row * 8 + (kc ^ (row & 7))) * 16);
}
__device__ __forceinline__ uint4 pack_bf16x8(float4 x, float4 y) {
    __nv_bfloat162 p0 = __float22bfloat162_rn(make_float2(x.x, x.y));
    __nv_bfloat162 p1 = __float22bfloat162_rn(make_float2(x.z, x.w));
    __nv_bfloat162 p2 = __float22bfloat162_rn(make_float2(y.x, y.y));
    __nv_bfloat162 p3 = __float22bfloat162_rn(make_float2(y.z, y.w));
    uint4 o;
    o.x = *reinterpret_cast<unsigned*>(&p0);
    o.y = *reinterpret_cast<unsigned*>(&p1);
    o.z = *reinterpret_cast<unsigned*>(&p2);
    o.w = *reinterpret_cast<unsigned*>(&p3);
    return o;
}

// ---------------------------------------------------------------------------
// Kernel 1 (merged prep, ONE launch):
//   blocks [0, ENC_BLK)                 : enc fp32 -> bf16
//   blocks [ENC_BLK, ENC_BLK+UW_BLK)    : U_w fp32 -> bf16
//   blocks [ENC_BLK+UW_BLK, ...+WH_BLK) : g_WhT[h*64+b] = hidden·W_w + W_b + U_b
// ---------------------------------------------------------------------------
__global__ void __launch_bounds__(256, 4)
prep_kernel(const float* __restrict__ enc, const float* __restrict__ Uw,
            const float* __restrict__ hidden, const float* __restrict__ W_w,
            const float* __restrict__ W_b, const float* __restrict__ U_b) {
    __shared__ float4 sh[8][256];
    const int tid = threadIdx.x;
    if (blockIdx.x < ENC_BLK) {
        const size_t g = (size_t)blockIdx.x * 256 + tid;
        const float4* s = (const float4*)enc + 2 * g;
        ((uint4*)g_encB)[g] = pack_bf16x8(s[0], s[1]);
        return;
    }
    if (blockIdx.x < ENC_BLK + UW_BLK) {
        const size_t g = (size_t)(blockIdx.x - ENC_BLK) * 256 + tid;
        const float4* s = (const float4*)Uw + 2 * g;
        ((uint4*)g_UwB)[g] = pack_bf16x8(s[0], s[1]);
        return;
    }
    const int bid = blockIdx.x - ENC_BLK - UW_BLK;   // wh: 128 h-grp x 8 b-grp
    const int h0 = (bid >> 3) * 8, b0 = (bid & 7) * 8;
    for (int i = tid; i < 8 * 256; i += 256) {
        int bl = i >> 8, k4 = i & 255;
        sh[bl][k4] = reinterpret_cast<const float4*>(hidden)[(size_t)(b0 + bl) * 256 + k4];
    }
    __syncthreads();
    const int w = tid >> 5, lane = tid & 31;
    const int h = h0 + w;
    const float4* wrow = reinterpret_cast<const float4*>(W_w) + (size_t)h * 256;
    float acc[8] = {0.f, 0.f, 0.f, 0.f, 0.f, 0.f, 0.f, 0.f};
    for (int k4 = lane; k4 < 256; k4 += 32) {
        float4 wv = wrow[k4];
#pragma unroll
        for (int b = 0; b < 8; ++b) {
            float4 hv = sh[b][k4];
            acc[b] += wv.x * hv.x + wv.y * hv.y + wv.z * hv.z + wv.w * hv.w;
        }
    }
#pragma unroll
    for (int off = 16; off > 0; off >>= 1)
#pragma unroll
        for (int b = 0; b < 8; ++b) acc[b] += __shfl_xor_sync(0xffffffffu, acc[b], off);
    if (lane < 8)
        g_WhT[(size_t)h * 64 + b0 + lane] = acc[lane] + W_b[h] + U_b[h];
}

// ---------------------------------------------------------------------------
// Kernel 2: bf16 mma.sync GEMM (BM=128, BN=128, K=2048) + fused v·tanh epilogue.
// 128 threads = 4 warps (2m x 2n), warp tile 64x64, m16n8k16, ldmatrix feeds.
// 2x2 warp grid: each A/B fragment re-read only 2x -> smem traffic/stage drops
// 96KB -> 64KB of ldmatrix + 32KB cp.async, removing the crossbar co-bind.
// ring-3, ONE barrier/stage, loads issued AFTER compute(t) (race-free, R12).
// grid (Hh/128 = 8, Mm/128 = 256): n-block fastest -> A tile L2 reuse.
// ---------------------------------------------------------------------------
__global__ void __launch_bounds__(128, 2)
gemm_energy_mma(const float* __restrict__ v) {
    extern __shared__ char smem[];
    const uint32_t sbase = smem_u32(smem);

    const int tid = threadIdx.x;
    const int n0 = blockIdx.x * BN;
    const int m0 = blockIdx.y * BM;

    // ---- cp.async geometry: 128 threads, 16 chunks/thread (8 A + 8 B).
    // chunk: row = crow + 16*i, kc = ckc (row&7 invariant under +16)
    const int crow = tid >> 3, ckc = tid & 7;          // crow 0..15
    const char* srcA0 = (const char*)(g_encB + (size_t)(m0 + crow) * Kd) + ckc * 16;
    const char* srcB0 = (const char*)(g_UwB + (size_t)(n0 + crow) * Kd) + ckc * 16;
    const uint32_t dstA0 = tile_off(crow, ckc);
    const uint32_t dstB0 = (uint32_t)A_BYTES + tile_off(crow, ckc);
    constexpr size_t SRC_STEP = (size_t)16 * Kd * 2;   // 16 bf16 rows
    constexpr uint32_t DST_STEP = 16 * 8 * 16;         // 2048 B

    auto load_stage = [&](int t) {
        const uint32_t base = sbase + (uint32_t)(t % NRING) * STG_BYTES;
        const size_t ko = (size_t)t * (BK * 2);        // 128 B per stage
#pragma unroll
        for (int i = 0; i < 8; ++i)
            cp16(base + dstA0 + i * DST_STEP, srcA0 + ko + i * SRC_STEP);
#pragma unroll
        for (int i = 0; i < 8; ++i)
            cp16(base + dstB0 + i * DST_STEP, srcB0 + ko + i * SRC_STEP);
        cp_commit();
    };

    load_stage(0);
    load_stage(1);

    const int wid = tid >> 5, lane = tid & 31;
    const int wm = wid >> 1, wn = wid & 1;     // warp grid 2(m) x 2(n)
    const int gid = lane >> 2, tig = lane & 3;

    // ---- ldmatrix per-lane addresses (canonical bf16 m16n8k16 fragments)
    const uint32_t s7 = lane & 7;
    const uint32_t kcA = lane >> 4;            // 0/1
    const uint32_t kcB = (lane >> 3) & 1;      // 0/1
    uint32_t offA[4], offB[4];
#pragma unroll
    for (int mt = 0; mt < 4; ++mt)
        offA[mt] = (uint32_t)(wm * 64 + mt * 16 + (lane & 15)) * 128;
    const uint32_t rowBoff = (lane & 7) + ((lane >> 4) << 3);
#pragma unroll
    for (int p = 0; p < 4; ++p)
        offB[p] = (uint32_t)A_BYTES + (uint32_t)(wn * 64 + p * 16 + rowBoff) * 128;
    uint32_t coffA[4], coffB[4];
#pragma unroll
    for (int ks = 0; ks < 4; ++ks) {           // ks = one k16 step = chunks 2ks, 2ks+1
        coffA[ks] = ((2 * ks + kcA) ^ s7) * 16;
        coffB[ks] = ((2 * ks + kcB) ^ s7) * 16;
    }

    float c[4][8][4];
#pragma unroll
    for (int mt = 0; mt < 4; ++mt)
#pragma unroll
        for (int nt = 0; nt < 8; ++nt)
#pragma unroll
            for (int k = 0; k < 4; ++k) c[mt][nt][k] = 0.f;

    for (int t = 0; t < NSTG; ++t) {
        if (t < NSTG - 1) cp_wait<1>();
        else cp_wait<0>();
        __syncthreads();

        const uint32_t stb = sbase + (uint32_t)(t % NRING) * STG_BYTES;

#pragma unroll
        for (int ks = 0; ks < 4; ++ks) {
            uint32_t a[4][4];
#pragma unroll
            for (int mt = 0; mt < 4; ++mt)
                ldm4(a[mt][0], a[mt][1], a[mt][2], a[mt][3],
                     stb + offA[mt] + coffA[ks]);
            uint32_t b[8][2];
#pragma unroll
            for (int p = 0; p < 4; ++p)
                ldm4(b[2 * p][0], b[2 * p][1], b[2 * p + 1][0], b[2 * p + 1][1],
                     stb + offB[p] + coffB[ks]);
#pragma unroll
            for (int mt = 0; mt < 4; ++mt)
#pragma unroll
                for (int nt = 0; nt < 8; ++nt)
                    mma_bf16(c[mt][nt], a[mt][0], a[mt][1], a[mt][2], a[mt][3],
                             b[nt][0], b[nt][1]);
        }

        // prefetch AFTER compute(t): past barrier(t) -> compute(t-1) done in
        // all threads -> slot (t+2)%3 == (t-1)%3 safe to overwrite.
        if (t + 2 < NSTG) load_stage(t + 2);
    }

    // ---- fused epilogue: pe = sum over held cols of v[h]*tanh(C + WhT[h][b])
    float pe[4][2];
#pragma unroll
    for (int mt = 0; mt < 4; ++mt) { pe[mt][0] = 0.f; pe[mt][1] = 0.f; }

#pragma unroll
    for (int nt = 0; nt < 8; ++nt) {
        const int h0 = n0 + wn * 64 + nt * 8 + 2 * tig;
        const float vh0 = __ldg(&v[h0]);
        const float vh1 = __ldg(&v[h0 + 1]);
#pragma unroll
        for (int mt = 0; mt < 4; ++mt) {
#pragma unroll
            for (int half = 0; half < 2; ++half) {
                const int b = (mt * 16 + half * 8 + gid) & 63;  // (m0+row)&63; wm*64≡0 (mod 64)
                const float w0 = __ldg(&g_WhT[(size_t)h0 * 64 + b]);
                const float w1 = __ldg(&g_WhT[(size_t)(h0 + 1) * 64 + b]);
                pe[mt][half] += vh0 * tanhf(c[mt][nt][half * 2 + 0] + w0)
                              + vh1 * tanhf(c[mt][nt][half * 2 + 1] + w1);
            }
        }
    }

    // cross-warp reduction over the 2 n-warps (wn)
    __syncthreads();
    float* sred = (float*)smem;
#pragma unroll
    for (int mt = 0; mt < 4; ++mt)
#pragma unroll
        for (int half = 0; half < 2; ++half) {
            float s = pe[mt][half];
            s += __shfl_xor_sync(0xffffffffu, s, 1);
            s += __shfl_xor_sync(0xffffffffu, s, 2);
            if (tig == 0)
                sred[wn * 128 + wm * 64 + mt * 16 + half * 8 + gid] = s;
        }
    __syncthreads();
    {
        float s = sred[tid] + sred[128 + tid];
        g_partial[(size_t)(m0 + tid) * 8 + blockIdx.x] = s;
    }
}

// ---------------------------------------------------------------------------
// Kernel 3: masked softmax over S per batch. grid 64, block 512.
// ---------------------------------------------------------------------------
__global__ void softmax_kernel(const int* __restrict__ mask, float* __restrict__ out) {
    const int b = blockIdx.x;
    const int s = threadIdx.x;
    const int m = s * Bb + b;
    float e = 0.f;
#pragma unroll
    for (int nb = 0; nb < 8; ++nb) e += g_partial[(size_t)m * 8 + nb];
    if (mask[b * Ss + s] != 0) e = NEGV;

    __shared__ float red[512];
    red[s] = e;
    __syncthreads();
    for (int off = 256; off > 0; off >>= 1) {
        if (s < off) red[s] = fmaxf(red[s], red[s + off]);
        __syncthreads();
    }
    const float mx = red[0];
    __syncthreads();
    const float ex = __expf(e - mx);
    red[s] = ex;
    __syncthreads();
    for (int off = 256; off > 0; off >>= 1) {
        if (s < off) red[s] += red[s + off];
        __syncthreads();
    }
    out[b * Ss + s] = ex / red[0];
}

// ---------------------------------------------------------------------------
extern "C" void kernel_launch(void* const* d_in, const int* in_sizes, int n_in,
                              void* d_out, int out_size) {
    const float* hidden = (const float*)d_in[0];
    const float* enc    = (const float*)d_in[1];   // [S,B,2H] == [Mm,Kd]
    const int*   mask   = (const int*)d_in[2];
    const float* W_w    = (const float*)d_in[3];
    const float* W_b    = (const float*)d_in[4];
    const float* U_w    = (const float*)d_in[5];
    const float* U_b    = (const float*)d_in[6];
    const float* v_w    = (const float*)d_in[7];
    float* out = (float*)d_out;

    cudaFuncSetAttribute(gemm_energy_mma, cudaFuncAttributeMaxDynamicSharedMemorySize,
                         GEMM_SMEM);

    prep_kernel<<<ENC_BLK + UW_BLK + WH_BLK, 256>>>(enc, U_w, hidden, W_w, W_b, U_b);
    gemm_energy_mma<<<dim3(Hh / BN, Mm / BM), 128, GEMM_SMEM>>>(v_w);
    softmax_kernel<<<Bb, 512>>>(mask, out);
}

// round 16
// speedup vs baseline: 1.2088x; 1.0670x over previous
#include <cuda_runtime.h>
#include <cuda_bf16.h>
#include <cstdint>
#include <math.h>

// Problem constants
constexpr int Bb = 64, Ss = 512, Hh = 1024, Kd = 2048, Mm = Bb * Ss;
#define NEGV -1e10f

// Scratch (no cudaMalloc allowed)
__device__ float g_WhT[Hh * Bb];      // WhT[h*64+b] = hidden@W^T + W_b + U_b (folded)
__device__ float g_partial[Mm * 8];   // per-(m, n-block) energy partials
__device__ __nv_bfloat16 g_encB[(size_t)Mm * Kd];   // 128 MB bf16 enc
__device__ __nv_bfloat16 g_UwB[(size_t)Hh * Kd];    // 4 MB bf16 U_w

// ---------------- GEMM tiling (bf16) ----------------
constexpr int BM = 128, BN = 128, BK = 64;     // BK=64 bf16 = 128B rows
constexpr int NSTG = Kd / BK;                  // 32 K-stages
constexpr int A_BYTES = BM * BK * 2;           // 16 KB
constexpr int B_BYTES = BN * BK * 2;           // 16 KB
constexpr int STG_BYTES = A_BYTES + B_BYTES;   // 32 KB
constexpr int NRING = 3;                       // ring-3; load AFTER compute -> safe
constexpr int GEMM_SMEM = NRING * STG_BYTES;   // 96 KB -> 2 CTAs/SM

// prep kernel block ranges (enc part: 2 chunks of 16B per thread)
constexpr int ENC_BLK = (Mm * (size_t)Kd) / (8 * 256 * 2);  // 16384
constexpr int UW_BLK  = (Hh * (size_t)Kd) / (8 * 256);      // 1024
constexpr int WH_BLK  = (Hh / 8) * (Bb / 8);                // 1024

// ---------------- helpers ----------------
__device__ __forceinline__ uint32_t smem_u32(const void* p) {
    uint32_t a;
    asm("{ .reg .u64 t; cvta.to.shared.u64 t, %1; cvt.u32.u64 %0, t; }" : "=r"(a) : "l"(p));
    return a;
}
__device__ __forceinline__ void cp16(uint32_t dst, const void* src) {
    asm volatile("cp.async.cg.shared.global [%0], [%1], 16;" :: "r"(dst), "l"(src));
}
__device__ __forceinline__ void cp_commit() {
    asm volatile("cp.async.commit_group;" ::: "memory");
}
template <int N> __device__ __forceinline__ void cp_wait() {
    asm volatile("cp.async.wait_group %0;" :: "n"(N) : "memory");
}
__device__ __forceinline__ void ldm4(uint32_t& d0, uint32_t& d1, uint32_t& d2,
                                     uint32_t& d3, uint32_t addr) {
    asm volatile("ldmatrix.sync.aligned.m8n8.x4.shared.b16 {%0,%1,%2,%3}, [%4];"
                 : "=r"(d0), "=r"(d1), "=r"(d2), "=r"(d3) : "r"(addr));
}
__device__ __forceinline__ void mma_bf16(float c[4], uint32_t a0, uint32_t a1,
                                         uint32_t a2, uint32_t a3,
                                         uint32_t b0, uint32_t b1) {
    asm volatile("mma.sync.aligned.m16n8k16.row.col.f32.bf16.bf16.f32 "
                 "{%0,%1,%2,%3}, {%4,%5,%6,%7}, {%8,%9}, {%0,%1,%2,%3};"
                 : "+f"(c[0]), "+f"(c[1]), "+f"(c[2]), "+f"(c[3])
                 : "r"(a0), "r"(a1), "r"(a2), "r"(a3), "r"(b0), "r"(b1));
}
__device__ __forceinline__ float tanh_ap(float x) {
    float y;
    asm("tanh.approx.f32 %0, %1;" : "=f"(y) : "f"(x));
    return y;
}
// swizzled 16B-chunk offset within a tile: rows of 8 chunks, chunk column
// XOR'd with (row&7) -> ldmatrix and cp.async STS both conflict-free
__device__ __forceinline__ uint32_t tile_off(int row, int kc) {
    return (uint32_t)((row * 8 + (kc ^ (row & 7))) * 16);
}
__device__ __forceinline__ uint4 pack_bf16x8(float4 x, float4 y) {
    __nv_bfloat162 p0 = __float22bfloat162_rn(make_float2(x.x, x.y));
    __nv_bfloat162 p1 = __float22bfloat162_rn(make_float2(x.z, x.w));
    __nv_bfloat162 p2 = __float22bfloat162_rn(make_float2(y.x, y.y));
    __nv_bfloat162 p3 = __float22bfloat162_rn(make_float2(y.z, y.w));
    uint4 o;
    o.x = *reinterpret_cast<unsigned*>(&p0);
    o.y = *reinterpret_cast<unsigned*>(&p1);
    o.z = *reinterpret_cast<unsigned*>(&p2);
    o.w = *reinterpret_cast<unsigned*>(&p3);
    return o;
}

// ---------------------------------------------------------------------------
// Kernel 1 (merged prep, ONE launch):
//   blocks [0, ENC_BLK)                 : enc fp32 -> bf16 (2 chunks/thread,
//                                         streaming hints, MLP=4)
//   blocks [ENC_BLK, ENC_BLK+UW_BLK)    : U_w fp32 -> bf16
//   blocks [ENC_BLK+UW_BLK, ...+WH_BLK) : g_WhT[h*64+b] = hidden·W_w + W_b + U_b
// ---------------------------------------------------------------------------
__global__ void __launch_bounds__(256, 4)
prep_kernel(const float* __restrict__ enc, const float* __restrict__ Uw,
            const float* __restrict__ hidden, const float* __restrict__ W_w,
            const float* __restrict__ W_b, const float* __restrict__ U_b) {
    __shared__ float4 sh[8][256];
    const int tid = threadIdx.x;
    if (blockIdx.x < ENC_BLK) {
        const size_t g0 = (size_t)blockIdx.x * 512 + tid;   // chunks g0, g0+256
        const float4* s0 = (const float4*)enc + 2 * g0;
        const float4* s1 = (const float4*)enc + 2 * (g0 + 256);
        float4 a0 = __ldcs(s0 + 0), a1 = __ldcs(s0 + 1);
        float4 b0 = __ldcs(s1 + 0), b1 = __ldcs(s1 + 1);
        __stcs((uint4*)g_encB + g0, pack_bf16x8(a0, a1));
        __stcs((uint4*)g_encB + g0 + 256, pack_bf16x8(b0, b1));
        return;
    }
    if (blockIdx.x < ENC_BLK + UW_BLK) {
        const size_t g = (size_t)(blockIdx.x - ENC_BLK) * 256 + tid;
        const float4* s = (const float4*)Uw + 2 * g;
        ((uint4*)g_UwB)[g] = pack_bf16x8(s[0], s[1]);
        return;
    }
    const int bid = blockIdx.x - ENC_BLK - UW_BLK;   // wh: 128 h-grp x 8 b-grp
    const int h0 = (bid >> 3) * 8, b0 = (bid & 7) * 8;
    for (int i = tid; i < 8 * 256; i += 256) {
        int bl = i >> 8, k4 = i & 255;
        sh[bl][k4] = reinterpret_cast<const float4*>(hidden)[(size_t)(b0 + bl) * 256 + k4];
    }
    __syncthreads();
    const int w = tid >> 5, lane = tid & 31;
    const int h = h0 + w;
    const float4* wrow = reinterpret_cast<const float4*>(W_w) + (size_t)h * 256;
    float acc[8] = {0.f, 0.f, 0.f, 0.f, 0.f, 0.f, 0.f, 0.f};
    for (int k4 = lane; k4 < 256; k4 += 32) {
        float4 wv = wrow[k4];
#pragma unroll
        for (int b = 0; b < 8; ++b) {
            float4 hv = sh[b][k4];
            acc[b] += wv.x * hv.x + wv.y * hv.y + wv.z * hv.z + wv.w * hv.w;
        }
    }
#pragma unroll
    for (int off = 16; off > 0; off >>= 1)
#pragma unroll
        for (int b = 0; b < 8; ++b) acc[b] += __shfl_xor_sync(0xffffffffu, acc[b], off);
    if (lane < 8)
        g_WhT[(size_t)h * 64 + b0 + lane] = acc[lane] + W_b[h] + U_b[h];
}

// ---------------------------------------------------------------------------
// Kernel 2: bf16 mma.sync GEMM (BM=128, BN=128, K=2048) + fused v·tanh epilogue.
// 128 threads = 4 warps (2m x 2n), warp tile 64x64, m16n8k16, ldmatrix feeds.
// ring-3, ONE barrier/stage, loads issued AFTER compute(t) (race-free, R12).
// 96KB smem -> 2 CTAs/SM. grid (Hh/128 = 8, Mm/128 = 256), n-block fastest.
// ---------------------------------------------------------------------------
__global__ void __launch_bounds__(128, 2)
gemm_energy_mma(const float* __restrict__ v) {
    extern __shared__ char smem[];
    const uint32_t sbase = smem_u32(smem);

    const int tid = threadIdx.x;
    const int n0 = blockIdx.x * BN;
    const int m0 = blockIdx.y * BM;

    // ---- cp.async geometry: 128 threads, 16 chunks/thread (8 A + 8 B).
    const int crow = tid >> 3, ckc = tid & 7;          // crow 0..15
    const char* srcA0 = (const char*)(g_encB + (size_t)(m0 + crow) * Kd) + ckc * 16;
    const char* srcB0 = (const char*)(g_UwB + (size_t)(n0 + crow) * Kd) + ckc * 16;
    const uint32_t dstA0 = tile_off(crow, ckc);
    const uint32_t dstB0 = (uint32_t)A_BYTES + tile_off(crow, ckc);
    constexpr size_t SRC_STEP = (size_t)16 * Kd * 2;   // 16 bf16 rows
    constexpr uint32_t DST_STEP = 16 * 8 * 16;         // 2048 B

    auto load_stage = [&](int t) {
        const uint32_t base = sbase + (uint32_t)(t % NRING) * STG_BYTES;
        const size_t ko = (size_t)t * (BK * 2);        // 128 B per stage
#pragma unroll
        for (int i = 0; i < 8; ++i)
            cp16(base + dstA0 + i * DST_STEP, srcA0 + ko + i * SRC_STEP);
#pragma unroll
        for (int i = 0; i < 8; ++i)
            cp16(base + dstB0 + i * DST_STEP, srcB0 + ko + i * SRC_STEP);
        cp_commit();
    };

    load_stage(0);
    load_stage(1);

    const int wid = tid >> 5, lane = tid & 31;
    const int wm = wid >> 1, wn = wid & 1;     // warp grid 2(m) x 2(n)
    const int gid = lane >> 2, tig = lane & 3;

    // ---- ldmatrix per-lane addresses (canonical bf16 m16n8k16 fragments)
    const uint32_t s7 = lane & 7;
    const uint32_t kcA = lane >> 4;            // 0/1
    const uint32_t kcB = (lane >> 3) & 1;      // 0/1
    uint32_t offA[4], offB[4];
#pragma unroll
    for (int mt = 0; mt < 4; ++mt)
        offA[mt] = (uint32_t)(wm * 64 + mt * 16 + (lane & 15)) * 128;
    const uint32_t rowBoff = (lane & 7) + ((lane >> 4) << 3);
#pragma unroll
    for (int p = 0; p < 4; ++p)
        offB[p] = (uint32_t)A_BYTES + (uint32_t)(wn * 64 + p * 16 + rowBoff) * 128;
    uint32_t coffA[4], coffB[4];
#pragma unroll
    for (int ks = 0; ks < 4; ++ks) {           // ks = one k16 step = chunks 2ks, 2ks+1
        coffA[ks] = ((2 * ks + kcA) ^ s7) * 16;
        coffB[ks] = ((2 * ks + kcB) ^ s7) * 16;
    }

    float c[4][8][4];
#pragma unroll
    for (int mt = 0; mt < 4; ++mt)
#pragma unroll
        for (int nt = 0; nt < 8; ++nt)
#pragma unroll
            for (int k = 0; k < 4; ++k) c[mt][nt][k] = 0.f;

    for (int t = 0; t < NSTG; ++t) {
        if (t < NSTG - 1) cp_wait<1>();
        else cp_wait<0>();
        __syncthreads();

        const uint32_t stb = sbase + (uint32_t)(t % NRING) * STG_BYTES;

#pragma unroll
        for (int ks = 0; ks < 4; ++ks) {
            uint32_t a[4][4];
#pragma unroll
            for (int mt = 0; mt < 4; ++mt)
                ldm4(a[mt][0], a[mt][1], a[mt][2], a[mt][3],
                     stb + offA[mt] + coffA[ks]);
            uint32_t b[8][2];
#pragma unroll
            for (int p = 0; p < 4; ++p)
                ldm4(b[2 * p][0], b[2 * p][1], b[2 * p + 1][0], b[2 * p + 1][1],
                     stb + offB[p] + coffB[ks]);
#pragma unroll
            for (int mt = 0; mt < 4; ++mt)
#pragma unroll
                for (int nt = 0; nt < 8; ++nt)
                    mma_bf16(c[mt][nt], a[mt][0], a[mt][1], a[mt][2], a[mt][3],
                             b[nt][0], b[nt][1]);
        }

        // prefetch AFTER compute(t): past barrier(t) -> compute(t-1) done in
        // all threads -> slot (t+2)%3 == (t-1)%3 safe to overwrite.
        if (t + 2 < NSTG) load_stage(t + 2);
    }

    // ---- fused epilogue: pe = sum over held cols of v[h]*tanh(C + WhT[h][b])
    float pe[4][2];
#pragma unroll
    for (int mt = 0; mt < 4; ++mt) { pe[mt][0] = 0.f; pe[mt][1] = 0.f; }

#pragma unroll
    for (int nt = 0; nt < 8; ++nt) {
        const int h0 = n0 + wn * 64 + nt * 8 + 2 * tig;
        const float vh0 = __ldg(&v[h0]);
        const float vh1 = __ldg(&v[h0 + 1]);
#pragma unroll
        for (int mt = 0; mt < 4; ++mt) {
#pragma unroll
            for (int half = 0; half < 2; ++half) {
                const int b = (mt * 16 + half * 8 + gid) & 63;  // (m0+row)&63
                const float w0 = __ldg(&g_WhT[(size_t)h0 * 64 + b]);
                const float w1 = __ldg(&g_WhT[(size_t)(h0 + 1) * 64 + b]);
                pe[mt][half] += vh0 * tanh_ap(c[mt][nt][half * 2 + 0] + w0)
                              + vh1 * tanh_ap(c[mt][nt][half * 2 + 1] + w1);
            }
        }
    }

    // cross-warp reduction over the 2 n-warps (wn)
    __syncthreads();
    float* sred = (float*)smem;
#pragma unroll
    for (int mt = 0; mt < 4; ++mt)
#pragma unroll
        for (int half = 0; half < 2; ++half) {
            float s = pe[mt][half];
            s += __shfl_xor_sync(0xffffffffu, s, 1);
            s += __shfl_xor_sync(0xffffffffu, s, 2);
            if (tig == 0)
                sred[wn * 128 + wm * 64 + mt * 16 + half * 8 + gid] = s;
        }
    __syncthreads();
    {
        float s = sred[tid] + sred[128 + tid];
        g_partial[(size_t)(m0 + tid) * 8 + blockIdx.x] = s;
    }
}

// ---------------------------------------------------------------------------
// Kernel 3: masked softmax over S per batch. grid 64, block 512.
// ---------------------------------------------------------------------------
__global__ void softmax_kernel(const int* __restrict__ mask, float* __restrict__ out) {
    const int b = blockIdx.x;
    const int s = threadIdx.x;
    const int m = s * Bb + b;
    float e = 0.f;
#pragma unroll
    for (int nb = 0; nb < 8; ++nb) e += g_partial[(size_t)m * 8 + nb];
    if (mask[b * Ss + s] != 0) e = NEGV;

    __shared__ float red[512];
    red[s] = e;
    __syncthreads();
    for (int off = 256; off > 0; off >>= 1) {
        if (s < off) red[s] = fmaxf(red[s], red[s + off]);
        __syncthreads();
    }
    const float mx = red[0];
    __syncthreads();
    const float ex = __expf(e - mx);
    red[s] = ex;
    __syncthreads();
    for (int off = 256; off > 0; off >>= 1) {
        if (s < off) red[s] += red[s + off];
        __syncthreads();
    }
    out[b * Ss + s] = ex / red[0];
}

// ---------------------------------------------------------------------------
extern "C" void kernel_launch(void* const* d_in, const int* in_sizes, int n_in,
                              void* d_out, int out_size) {
    const float* hidden = (const float*)d_in[0];
    const float* enc    = (const float*)d_in[1];   // [S,B,2H] == [Mm,Kd]
    const int*   mask   = (const int*)d_in[2];
    const float* W_w    = (const float*)d_in[3];
    const float* W_b    = (const float*)d_in[4];
    const float* U_w    = (const float*)d_in[5];
    const float* U_b    = (const float*)d_in[6];
    const float* v_w    = (const float*)d_in[7];
    float* out = (float*)d_out;

    cudaFuncSetAttribute(gemm_energy_mma, cudaFuncAttributeMaxDynamicSharedMemorySize,
                         GEMM_SMEM);

    prep_kernel<<<ENC_BLK + UW_BLK + WH_BLK, 256>>>(enc, U_w, hidden, W_w, W_b, U_b);
    gemm_energy_mma<<<dim3(Hh / BN, Mm / BM), 128, GEMM_SMEM>>>(v_w);
    softmax_kernel<<<Bb, 512>>>(mask, out);
}